// round 6
// baseline (speedup 1.0000x reference)
#include <cuda_runtime.h>
#include <mma.h>
#include <cstdint>

using namespace nvcuda;

// Fixed shapes per reference
#define NN     50000
#define NPAD   50048    // ceil(NN/64)*64 — wmma stores may touch padding rows
#define IN_F   256
#define H_F    128
#define OUT_F  64
#define EMAX   800000

// ---------------------------------------------------------------------------
// Static device scratch (no allocation allowed).
// ---------------------------------------------------------------------------
__device__ __align__(32) float g_t[(size_t)NPAD * H_F];  // GEMM output buffer
__device__ __align__(32) float g_a[(size_t)NN * H_F];    // hidden activations
__device__ float g_dinv[NN];
__device__ int   g_cnt[NN];
__device__ int   g_off[NN + 1];
__device__ int   g_col[EMAX];
__device__ int   g_bsum[256];
__device__ int   g_is64;

// ---------------------------------------------------------------------------
// Edge width autodetect: int64 values < 2^32 => every odd int32 word is 0.
// ---------------------------------------------------------------------------
__global__ void detect_kernel(const int* __restrict__ ei32) {
    if (threadIdx.x == 0 && blockIdx.x == 0) {
        int allzero = 1;
        for (int i = 0; i < 64; i++)
            if (ei32[2 * i + 1] != 0) { allzero = 0; break; }
        g_is64 = allzero;
    }
}

__device__ __forceinline__ int edge_src(const int* ei, int E, int e) {
    return g_is64 ? ei[2 * (size_t)e] : ei[(size_t)e];
}
__device__ __forceinline__ int edge_dst(const int* ei, int E, int e) {
    return g_is64 ? ei[2 * ((size_t)E + e)] : ei[(size_t)E + e];
}

// ---------------------------------------------------------------------------
// CSR build: zero -> histogram(dst) -> hierarchical scan -> scatter(src)
// ---------------------------------------------------------------------------
__global__ void zero_cnt_kernel(int n) {
    int i = blockIdx.x * blockDim.x + threadIdx.x;
    if (i < n) g_cnt[i] = 0;
}

__global__ void hist_kernel(const int* __restrict__ ei, int E) {
    int e = blockIdx.x * blockDim.x + threadIdx.x;
    if (e >= E) return;
    int d = edge_dst(ei, E, e);
    if ((unsigned)d < (unsigned)NN) atomicAdd(&g_cnt[d], 1);
}

__global__ void scan_local_kernel(int n) {
    __shared__ int sh[256];
    const int tid = threadIdx.x;
    const int i = blockIdx.x * 256 + tid;
    int v = (i < n) ? g_cnt[i] : 0;
    sh[tid] = v;
    __syncthreads();
#pragma unroll
    for (int off = 1; off < 256; off <<= 1) {
        int u = (tid >= off) ? sh[tid - off] : 0;
        __syncthreads();
        sh[tid] += u;
        __syncthreads();
    }
    if (i < n) g_off[i] = sh[tid] - v;
    if (tid == 255) g_bsum[blockIdx.x] = sh[255];
}

__global__ void scan_bsum_kernel(int nb) {
    __shared__ int sh[256];
    const int tid = threadIdx.x;
    int v = (tid < nb) ? g_bsum[tid] : 0;
    sh[tid] = v;
    __syncthreads();
#pragma unroll
    for (int off = 1; off < 256; off <<= 1) {
        int u = (tid >= off) ? sh[tid - off] : 0;
        __syncthreads();
        sh[tid] += u;
        __syncthreads();
    }
    if (tid < nb) g_bsum[tid] = sh[tid] - v;
}

__global__ void scan_apply_kernel(int n) {
    int i = blockIdx.x * 256 + threadIdx.x;
    if (i >= n) return;
    int base = g_bsum[blockIdx.x];
    int c = g_cnt[i];
    int o = g_off[i] + base;
    g_off[i] = o;
    g_dinv[i] = rsqrtf((float)(c + 1));
    g_cnt[i] = 0;
    if (i == n - 1) g_off[n] = o + c;
}

__global__ void scatter_kernel(const int* __restrict__ ei, int E) {
    int e = blockIdx.x * blockDim.x + threadIdx.x;
    if (e >= E) return;
    int s = edge_src(ei, E, e);
    int d = edge_dst(ei, E, e);
    if ((unsigned)s >= (unsigned)NN || (unsigned)d >= (unsigned)NN) return;
    int pos = g_off[d] + atomicAdd(&g_cnt[d], 1);
    g_col[pos] = s;
}

// ---------------------------------------------------------------------------
// Gather aggregation (no float atomics). One warp per dst node.
// ---------------------------------------------------------------------------
__global__ void agg1_kernel(const float* __restrict__ b1, int n) {
    int gw   = (blockIdx.x * blockDim.x + threadIdx.x) >> 5;
    int lane = threadIdx.x & 31;
    if (gw >= n) return;
    const float4* __restrict__ trow = reinterpret_cast<const float4*>(g_t);

    float wd = g_dinv[gw];
    float ws = wd * wd;
    float4 v = trow[(size_t)gw * 32 + lane];  // self-loop
    float4 acc = make_float4(v.x * ws, v.y * ws, v.z * ws, v.w * ws);

    int beg = g_off[gw], end = g_off[gw + 1];
    for (int e = beg; e < end; e++) {
        int s = g_col[e];
        float w = g_dinv[s] * wd;
        float4 u = trow[(size_t)s * 32 + lane];
        acc.x = fmaf(u.x, w, acc.x);
        acc.y = fmaf(u.y, w, acc.y);
        acc.z = fmaf(u.z, w, acc.z);
        acc.w = fmaf(u.w, w, acc.w);
    }
    float4 bb = reinterpret_cast<const float4*>(b1)[lane];
    acc.x = fmaxf(acc.x + bb.x, 0.f);
    acc.y = fmaxf(acc.y + bb.y, 0.f);
    acc.z = fmaxf(acc.z + bb.z, 0.f);
    acc.w = fmaxf(acc.w + bb.w, 0.f);
    reinterpret_cast<float4*>(g_a)[(size_t)gw * 32 + lane] = acc;
}

__global__ void agg2_kernel(const float* __restrict__ b2, float* __restrict__ out, int n) {
    int gw   = (blockIdx.x * blockDim.x + threadIdx.x) >> 5;
    int lane = threadIdx.x & 31;
    if (gw >= n) return;
    const float2* __restrict__ trow = reinterpret_cast<const float2*>(g_t);

    float wd = g_dinv[gw];
    float ws = wd * wd;
    float2 v = trow[(size_t)gw * 32 + lane];
    float2 acc = make_float2(v.x * ws, v.y * ws);

    int beg = g_off[gw], end = g_off[gw + 1];
    for (int e = beg; e < end; e++) {
        int s = g_col[e];
        float w = g_dinv[s] * wd;
        float2 u = trow[(size_t)s * 32 + lane];
        acc.x = fmaf(u.x, w, acc.x);
        acc.y = fmaf(u.y, w, acc.y);
    }
    float2 bb = reinterpret_cast<const float2*>(b2)[lane];
    acc.x += bb.x;
    acc.y += bb.y;
    reinterpret_cast<float2*>(out)[(size_t)gw * 32 + lane] = acc;
}

// ---------------------------------------------------------------------------
// Tensor-core GEMM: TF32 wmma with hi/lo compensation (3 MMAs per product).
// C[M,N] = A[M,K] @ B[K,N], C = g_t (padded to NPAD rows). 256 threads.
// Warp grid: (BM/WM) x (BN/WN) must equal 8 warps.
// ---------------------------------------------------------------------------
template<int BM, int BN, int BK, int WM, int WN>
__global__ void __launch_bounds__(256)
gemm_tf32_kernel(const float* __restrict__ Aext, int Asel,
                 const float* __restrict__ B, int M, int K, int N) {
    constexpr int BKP = BK + 8;          // row bytes multiple of 32
    constexpr int BNP = BN + 8;
    constexpr int WARPS_N = BN / WN;
    constexpr int AM = WM / 16;
    constexpr int AN = WN / 16;
    constexpr int KK = BK / 8;

    const float* __restrict__ A = Asel ? (const float*)g_a : Aext;
    float* __restrict__ C = g_t;

    __shared__ __align__(32) float As[BM * BKP];
    __shared__ __align__(32) float Bs[BK * BNP];

    const int tid = threadIdx.x;
    const int wid = tid >> 5;
    const int wm = wid / WARPS_N;
    const int wn = wid % WARPS_N;
    const int row0 = blockIdx.x * BM;

    wmma::fragment<wmma::accumulator, 16, 16, 8, float> acc[AM][AN];
#pragma unroll
    for (int m = 0; m < AM; m++)
#pragma unroll
        for (int n = 0; n < AN; n++) wmma::fill_fragment(acc[m][n], 0.f);

    for (int k0 = 0; k0 < K; k0 += BK) {
#pragma unroll
        for (int idx = tid; idx < BM * (BK / 4); idx += 256) {
            int i = idx / (BK / 4), q = idx % (BK / 4);
            int r = row0 + i;
            float4 v = (r < M) ? *reinterpret_cast<const float4*>(A + (size_t)r * K + k0 + q * 4)
                               : make_float4(0.f, 0.f, 0.f, 0.f);
            *reinterpret_cast<float4*>(As + i * BKP + q * 4) = v;
        }
#pragma unroll
        for (int idx = tid; idx < BK * (BN / 4); idx += 256) {
            int kk = idx / (BN / 4), q = idx % (BN / 4);
            *reinterpret_cast<float4*>(Bs + kk * BNP + q * 4) =
                *reinterpret_cast<const float4*>(B + (size_t)(k0 + kk) * N + q * 4);
        }
        __syncthreads();

#pragma unroll
        for (int kk = 0; kk < KK; kk++) {
            wmma::fragment<wmma::matrix_a, 16, 16, 8, wmma::precision::tf32, wmma::row_major> ahi[AM], alo[AM];
            wmma::fragment<wmma::matrix_b, 16, 16, 8, wmma::precision::tf32, wmma::row_major> bhi[AN], blo[AN];
#pragma unroll
            for (int m = 0; m < AM; m++) {
                const float* p = As + (wm * WM + m * 16) * BKP + kk * 8;
                wmma::load_matrix_sync(ahi[m], p, BKP);
                wmma::load_matrix_sync(alo[m], p, BKP);
#pragma unroll
                for (int t = 0; t < ahi[m].num_elements; t++) {
                    float v = ahi[m].x[t];
                    float h = wmma::__float_to_tf32(v);
                    ahi[m].x[t] = h;
                    alo[m].x[t] = wmma::__float_to_tf32(v - h);
                }
            }
#pragma unroll
            for (int n = 0; n < AN; n++) {
                const float* p = Bs + (kk * 8) * BNP + wn * WN + n * 16;
                wmma::load_matrix_sync(bhi[n], p, BNP);
                wmma::load_matrix_sync(blo[n], p, BNP);
#pragma unroll
                for (int t = 0; t < bhi[n].num_elements; t++) {
                    float v = bhi[n].x[t];
                    float h = wmma::__float_to_tf32(v);
                    bhi[n].x[t] = h;
                    blo[n].x[t] = wmma::__float_to_tf32(v - h);
                }
            }
#pragma unroll
            for (int m = 0; m < AM; m++)
#pragma unroll
                for (int n = 0; n < AN; n++) {
                    wmma::mma_sync(acc[m][n], alo[m], bhi[n], acc[m][n]);
                    wmma::mma_sync(acc[m][n], ahi[m], blo[n], acc[m][n]);
                    wmma::mma_sync(acc[m][n], ahi[m], bhi[n], acc[m][n]);
                }
        }
        __syncthreads();
    }

#pragma unroll
    for (int m = 0; m < AM; m++)
#pragma unroll
        for (int n = 0; n < AN; n++)
            wmma::store_matrix_sync(C + (size_t)(row0 + wm * WM + m * 16) * N + wn * WN + n * 16,
                                    acc[m][n], N, wmma::mem_row_major);
}

// ---------------------------------------------------------------------------
// Launch (graph-capturable, allocation-free)
// ---------------------------------------------------------------------------
extern "C" void kernel_launch(void* const* d_in, const int* in_sizes, int n_in,
                              void* d_out, int out_size) {
    const float* x   = (const float*)d_in[0];
    const int*   ei  = (const int*)d_in[1];
    const float* W1  = (const float*)d_in[2];
    const float* b1  = (const float*)d_in[3];
    const float* W2  = (const float*)d_in[4];
    const float* b2  = (const float*)d_in[5];
    float*       out = (float*)d_out;

    const int N = in_sizes[0] / IN_F;   // 50000
    const int E = in_sizes[1] / 2;      // 800000
    const int TB = 256;
    const int NB = (N + 255) / 256;

    // edge width detect + CSR build (dst-grouped) + dinv
    detect_kernel<<<1, 32>>>(ei);
    zero_cnt_kernel<<<(N + TB - 1) / TB, TB>>>(N);
    hist_kernel<<<(E + TB - 1) / TB, TB>>>(ei, E);
    scan_local_kernel<<<NB, 256>>>(N);
    scan_bsum_kernel<<<1, 256>>>(NB);
    scan_apply_kernel<<<NB, 256>>>(N);
    scatter_kernel<<<(E + TB - 1) / TB, TB>>>(ei, E);

    // layer 1: g_t = x @ W1 (TF32 tensor, compensated) ; g_a = relu(agg + b1)
    gemm_tf32_kernel<64, 128, 32, 32, 32><<<(N + 63) / 64, 256>>>(x, 0, W1, N, IN_F, H_F);
    agg1_kernel<<<(N + 7) / 8, 256>>>(b1, N);

    // layer 2: g_t = g_a @ W2 ; out = agg + b2
    gemm_tf32_kernel<64, 64, 32, 32, 16><<<(N + 63) / 64, 256>>>(nullptr, 1, W2, N, H_F, OUT_F);
    agg2_kernel<<<(N + 7) / 8, 256>>>(b2, out, N);
}

// round 7
// speedup vs baseline: 1.4812x; 1.4812x over previous
#include <cuda_runtime.h>
#include <cuda_bf16.h>
#include <mma.h>
#include <cstdint>

using namespace nvcuda;

// Fixed shapes per reference
#define NN     50000
#define NPAD   50048    // ceil(NN/64)*64 — wmma stores may touch padding rows
#define IN_F   256
#define H_F    128
#define OUT_F  64
#define EMAX   800000

// ---------------------------------------------------------------------------
// Static device scratch (no allocation allowed).
// ---------------------------------------------------------------------------
__device__ __align__(32) float g_t[(size_t)NPAD * H_F];  // GEMM output buffer
__device__ __align__(32) float g_a[(size_t)NN * H_F];    // hidden activations
__device__ float g_dinv[NN];
__device__ int   g_cnt[NN];
__device__ int   g_off[NN + 1];
__device__ int   g_col[EMAX];
__device__ int   g_bsum[256];
__device__ int   g_is64;

// ---------------------------------------------------------------------------
// Edge width autodetect: int64 values < 2^32 => every odd int32 word is 0.
// ---------------------------------------------------------------------------
__global__ void detect_kernel(const int* __restrict__ ei32) {
    if (threadIdx.x == 0 && blockIdx.x == 0) {
        int allzero = 1;
        for (int i = 0; i < 64; i++)
            if (ei32[2 * i + 1] != 0) { allzero = 0; break; }
        g_is64 = allzero;
    }
}

__device__ __forceinline__ int edge_src(const int* ei, int E, int e) {
    return g_is64 ? ei[2 * (size_t)e] : ei[(size_t)e];
}
__device__ __forceinline__ int edge_dst(const int* ei, int E, int e) {
    return g_is64 ? ei[2 * ((size_t)E + e)] : ei[(size_t)E + e];
}

// ---------------------------------------------------------------------------
// CSR build: zero -> histogram(dst) -> hierarchical scan -> scatter(src)
// ---------------------------------------------------------------------------
__global__ void zero_cnt_kernel(int n) {
    int i = blockIdx.x * blockDim.x + threadIdx.x;
    if (i < n) g_cnt[i] = 0;
}

__global__ void hist_kernel(const int* __restrict__ ei, int E) {
    int e = blockIdx.x * blockDim.x + threadIdx.x;
    if (e >= E) return;
    int d = edge_dst(ei, E, e);
    if ((unsigned)d < (unsigned)NN) atomicAdd(&g_cnt[d], 1);
}

__global__ void scan_local_kernel(int n) {
    __shared__ int sh[256];
    const int tid = threadIdx.x;
    const int i = blockIdx.x * 256 + tid;
    int v = (i < n) ? g_cnt[i] : 0;
    sh[tid] = v;
    __syncthreads();
#pragma unroll
    for (int off = 1; off < 256; off <<= 1) {
        int u = (tid >= off) ? sh[tid - off] : 0;
        __syncthreads();
        sh[tid] += u;
        __syncthreads();
    }
    if (i < n) g_off[i] = sh[tid] - v;
    if (tid == 255) g_bsum[blockIdx.x] = sh[255];
}

__global__ void scan_bsum_kernel(int nb) {
    __shared__ int sh[256];
    const int tid = threadIdx.x;
    int v = (tid < nb) ? g_bsum[tid] : 0;
    sh[tid] = v;
    __syncthreads();
#pragma unroll
    for (int off = 1; off < 256; off <<= 1) {
        int u = (tid >= off) ? sh[tid - off] : 0;
        __syncthreads();
        sh[tid] += u;
        __syncthreads();
    }
    if (tid < nb) g_bsum[tid] = sh[tid] - v;
}

__global__ void scan_apply_kernel(int n) {
    int i = blockIdx.x * 256 + threadIdx.x;
    if (i >= n) return;
    int base = g_bsum[blockIdx.x];
    int c = g_cnt[i];
    int o = g_off[i] + base;
    g_off[i] = o;
    g_dinv[i] = rsqrtf((float)(c + 1));
    g_cnt[i] = 0;
    if (i == n - 1) g_off[n] = o + c;
}

__global__ void scatter_kernel(const int* __restrict__ ei, int E) {
    int e = blockIdx.x * blockDim.x + threadIdx.x;
    if (e >= E) return;
    int s = edge_src(ei, E, e);
    int d = edge_dst(ei, E, e);
    if ((unsigned)s >= (unsigned)NN || (unsigned)d >= (unsigned)NN) return;
    int pos = g_off[d] + atomicAdd(&g_cnt[d], 1);
    g_col[pos] = s;
}

// ---------------------------------------------------------------------------
// Gather aggregation (no float atomics). One warp per dst node.
// ---------------------------------------------------------------------------
__global__ void agg1_kernel(const float* __restrict__ b1, int n) {
    int gw   = (blockIdx.x * blockDim.x + threadIdx.x) >> 5;
    int lane = threadIdx.x & 31;
    if (gw >= n) return;
    const float4* __restrict__ trow = reinterpret_cast<const float4*>(g_t);

    float wd = g_dinv[gw];
    float ws = wd * wd;
    float4 v = trow[(size_t)gw * 32 + lane];  // self-loop
    float4 acc = make_float4(v.x * ws, v.y * ws, v.z * ws, v.w * ws);

    int beg = g_off[gw], end = g_off[gw + 1];
    for (int e = beg; e < end; e++) {
        int s = g_col[e];
        float w = g_dinv[s] * wd;
        float4 u = trow[(size_t)s * 32 + lane];
        acc.x = fmaf(u.x, w, acc.x);
        acc.y = fmaf(u.y, w, acc.y);
        acc.z = fmaf(u.z, w, acc.z);
        acc.w = fmaf(u.w, w, acc.w);
    }
    float4 bb = reinterpret_cast<const float4*>(b1)[lane];
    acc.x = fmaxf(acc.x + bb.x, 0.f);
    acc.y = fmaxf(acc.y + bb.y, 0.f);
    acc.z = fmaxf(acc.z + bb.z, 0.f);
    acc.w = fmaxf(acc.w + bb.w, 0.f);
    reinterpret_cast<float4*>(g_a)[(size_t)gw * 32 + lane] = acc;
}

__global__ void agg2_kernel(const float* __restrict__ b2, float* __restrict__ out, int n) {
    int gw   = (blockIdx.x * blockDim.x + threadIdx.x) >> 5;
    int lane = threadIdx.x & 31;
    if (gw >= n) return;
    const float2* __restrict__ trow = reinterpret_cast<const float2*>(g_t);

    float wd = g_dinv[gw];
    float ws = wd * wd;
    float2 v = trow[(size_t)gw * 32 + lane];
    float2 acc = make_float2(v.x * ws, v.y * ws);

    int beg = g_off[gw], end = g_off[gw + 1];
    for (int e = beg; e < end; e++) {
        int s = g_col[e];
        float w = g_dinv[s] * wd;
        float2 u = trow[(size_t)s * 32 + lane];
        acc.x = fmaf(u.x, w, acc.x);
        acc.y = fmaf(u.y, w, acc.y);
    }
    float2 bb = reinterpret_cast<const float2*>(b2)[lane];
    acc.x += bb.x;
    acc.y += bb.y;
    reinterpret_cast<float2*>(out)[(size_t)gw * 32 + lane] = acc;
}

// ---------------------------------------------------------------------------
// Tensor-core GEMM: bf16 hi/lo compensated (3 MMAs per product, lo*lo dropped).
// Split happens ONCE per element during smem staging; inner loop is pure
// ldmatrix + HMMA. C[M,N] = A[M,K] @ B[K,N], C = g_t (NPAD rows). 256 threads.
// ---------------------------------------------------------------------------
__device__ __forceinline__ void split_bf16(float v, __nv_bfloat16& h, __nv_bfloat16& l) {
    h = __float2bfloat16_rn(v);
    l = __float2bfloat16_rn(v - __bfloat162float(h));
}

template<int BM, int BN, int BK, int WM, int WN>
__global__ void __launch_bounds__(256)
gemm_bf16_kernel(const float* __restrict__ Aext, int Asel,
                 const float* __restrict__ B, int M, int K, int N) {
    constexpr int BKP = BK + 16;      // bf16 elems; row stride 96B (32B multiple)
    constexpr int BNP = BN + 16;
    constexpr int WARPS_N = BN / WN;
    constexpr int AM = WM / 16;
    constexpr int AN = WN / 16;
    constexpr int KK = BK / 16;

    const float* __restrict__ A = Asel ? (const float*)g_a : Aext;
    float* __restrict__ C = g_t;

    __shared__ __align__(32) __nv_bfloat16 As_hi[BM * BKP];
    __shared__ __align__(32) __nv_bfloat16 As_lo[BM * BKP];
    __shared__ __align__(32) __nv_bfloat16 Bs_hi[BK * BNP];
    __shared__ __align__(32) __nv_bfloat16 Bs_lo[BK * BNP];

    const int tid = threadIdx.x;
    const int wid = tid >> 5;
    const int wm = wid / WARPS_N;
    const int wn = wid % WARPS_N;
    const int row0 = blockIdx.x * BM;

    wmma::fragment<wmma::accumulator, 16, 16, 16, float> acc[AM][AN];
#pragma unroll
    for (int m = 0; m < AM; m++)
#pragma unroll
        for (int n = 0; n < AN; n++) wmma::fill_fragment(acc[m][n], 0.f);

    for (int k0 = 0; k0 < K; k0 += BK) {
        // Stage + split A tile (BM x BK floats)
#pragma unroll
        for (int idx = tid; idx < BM * (BK / 4); idx += 256) {
            int i = idx / (BK / 4), q = idx % (BK / 4);
            int r = row0 + i;
            float4 v = (r < M) ? *reinterpret_cast<const float4*>(A + (size_t)r * K + k0 + q * 4)
                               : make_float4(0.f, 0.f, 0.f, 0.f);
            __nv_bfloat16 h0, l0, h1, l1, h2, l2, h3, l3;
            split_bf16(v.x, h0, l0); split_bf16(v.y, h1, l1);
            split_bf16(v.z, h2, l2); split_bf16(v.w, h3, l3);
            int o = i * BKP + q * 4;
            *reinterpret_cast<__nv_bfloat162*>(&As_hi[o])     = __nv_bfloat162(h0, h1);
            *reinterpret_cast<__nv_bfloat162*>(&As_hi[o + 2]) = __nv_bfloat162(h2, h3);
            *reinterpret_cast<__nv_bfloat162*>(&As_lo[o])     = __nv_bfloat162(l0, l1);
            *reinterpret_cast<__nv_bfloat162*>(&As_lo[o + 2]) = __nv_bfloat162(l2, l3);
        }
        // Stage + split B tile (BK x BN floats)
#pragma unroll
        for (int idx = tid; idx < BK * (BN / 4); idx += 256) {
            int kk = idx / (BN / 4), q = idx % (BN / 4);
            float4 v = *reinterpret_cast<const float4*>(B + (size_t)(k0 + kk) * N + q * 4);
            __nv_bfloat16 h0, l0, h1, l1, h2, l2, h3, l3;
            split_bf16(v.x, h0, l0); split_bf16(v.y, h1, l1);
            split_bf16(v.z, h2, l2); split_bf16(v.w, h3, l3);
            int o = kk * BNP + q * 4;
            *reinterpret_cast<__nv_bfloat162*>(&Bs_hi[o])     = __nv_bfloat162(h0, h1);
            *reinterpret_cast<__nv_bfloat162*>(&Bs_hi[o + 2]) = __nv_bfloat162(h2, h3);
            *reinterpret_cast<__nv_bfloat162*>(&Bs_lo[o])     = __nv_bfloat162(l0, l1);
            *reinterpret_cast<__nv_bfloat162*>(&Bs_lo[o + 2]) = __nv_bfloat162(l2, l3);
        }
        __syncthreads();

#pragma unroll
        for (int kk = 0; kk < KK; kk++) {
            wmma::fragment<wmma::matrix_a, 16, 16, 16, __nv_bfloat16, wmma::row_major> ahi[AM], alo[AM];
            wmma::fragment<wmma::matrix_b, 16, 16, 16, __nv_bfloat16, wmma::row_major> bhi[AN], blo[AN];
#pragma unroll
            for (int m = 0; m < AM; m++) {
                int o = (wm * WM + m * 16) * BKP + kk * 16;
                wmma::load_matrix_sync(ahi[m], As_hi + o, BKP);
                wmma::load_matrix_sync(alo[m], As_lo + o, BKP);
            }
#pragma unroll
            for (int n = 0; n < AN; n++) {
                int o = (kk * 16) * BNP + wn * WN + n * 16;
                wmma::load_matrix_sync(bhi[n], Bs_hi + o, BNP);
                wmma::load_matrix_sync(blo[n], Bs_lo + o, BNP);
            }
#pragma unroll
            for (int m = 0; m < AM; m++)
#pragma unroll
                for (int n = 0; n < AN; n++) {
                    wmma::mma_sync(acc[m][n], alo[m], bhi[n], acc[m][n]);
                    wmma::mma_sync(acc[m][n], ahi[m], blo[n], acc[m][n]);
                    wmma::mma_sync(acc[m][n], ahi[m], bhi[n], acc[m][n]);
                }
        }
        __syncthreads();
    }

#pragma unroll
    for (int m = 0; m < AM; m++)
#pragma unroll
        for (int n = 0; n < AN; n++)
            wmma::store_matrix_sync(C + (size_t)(row0 + wm * WM + m * 16) * N + wn * WN + n * 16,
                                    acc[m][n], N, wmma::mem_row_major);
}

// ---------------------------------------------------------------------------
// Launch (graph-capturable, allocation-free). GEMM1 placed 4th for profiling.
// ---------------------------------------------------------------------------
extern "C" void kernel_launch(void* const* d_in, const int* in_sizes, int n_in,
                              void* d_out, int out_size) {
    const float* x   = (const float*)d_in[0];
    const int*   ei  = (const int*)d_in[1];
    const float* W1  = (const float*)d_in[2];
    const float* b1  = (const float*)d_in[3];
    const float* W2  = (const float*)d_in[4];
    const float* b2  = (const float*)d_in[5];
    float*       out = (float*)d_out;

    const int N = in_sizes[0] / IN_F;   // 50000
    const int E = in_sizes[1] / 2;      // 800000
    const int TB = 256;
    const int NB = (N + 255) / 256;

    detect_kernel<<<1, 32>>>(ei);
    zero_cnt_kernel<<<(N + TB - 1) / TB, TB>>>(N);
    hist_kernel<<<(E + TB - 1) / TB, TB>>>(ei, E);

    // layer 1 GEMM at launch #4 (the slot ncu has been capturing)
    gemm_bf16_kernel<64, 128, 32, 32, 32><<<(N + 63) / 64, 256>>>(x, 0, W1, N, IN_F, H_F);

    scan_local_kernel<<<NB, 256>>>(N);
    scan_bsum_kernel<<<1, 256>>>(NB);
    scan_apply_kernel<<<NB, 256>>>(N);
    scatter_kernel<<<(E + TB - 1) / TB, TB>>>(ei, E);

    agg1_kernel<<<(N + 7) / 8, 256>>>(b1, N);

    gemm_bf16_kernel<64, 64, 32, 32, 16><<<(N + 63) / 64, 256>>>(nullptr, 1, W2, N, H_F, OUT_F);
    agg2_kernel<<<(N + 7) / 8, 256>>>(b2, out, N);
}